// round 3
// baseline (speedup 1.0000x reference)
#include <cuda_runtime.h>
#include <cuda_bf16.h>

// Upsample_910533067305: upfirdn2d(x, k=[1,3,3,1]^T[1,3,3,1]/16*4, up=2, pad=(2,1))
// Separable 2-tap blends:
//   out[2i]   = 0.25*x[i-1] + 0.75*x[i]
//   out[2i+1] = 0.75*x[i]   + 0.25*x[i+1]
// Output rows (2p-1, 2p) share input rows (p-1, p): one thread computes both.
// Wide tile: each thread covers 16 input cols (4x float4) per row -> 32 output
// cols x 2 rows. Misaligned halo cols (ix-1, ix+16) are 2 scalar LDGs per row,
// amortized over 64 outputs (4x better than the 121us version).

#define BC_   2048   // 16*128
#define H_    128
#define W_    128
#define OH_   256
#define OW_   256

__global__ __launch_bounds__(128)
void up2_kernel(const float* __restrict__ x, float* __restrict__ out) {
    const int tx = threadIdx.x;                            // 0..7, 16 input cols each
    const int p  = blockIdx.y * blockDim.y + threadIdx.y;  // row-pair index 0..128
    if (p > H_) return;
    const int bc = blockIdx.z;

    const int iy = p - 1;          // upper input row of the pair
    const int ix = tx * 16;        // first input col of this thread's span

    const float* base = x + (size_t)bc * (H_ * W_);
    const float* rowA = base + (size_t)iy * W_ + ix;
    const float* rowB = rowA + W_;

    const bool rA = (iy >= 0);
    const bool rB = (p < H_);      // iy+1 < H
    const bool cL = (ix > 0);
    const bool cR = (ix + 16 < W_);

    // a[k] / b[k] = input col (ix-1+k) of rows iy / iy+1, zero outside.
    float a[18], b[18];

    if (rA) {
        #pragma unroll
        for (int v = 0; v < 4; v++) {
            float4 m = reinterpret_cast<const float4*>(rowA)[v];
            a[4*v + 1] = m.x; a[4*v + 2] = m.y; a[4*v + 3] = m.z; a[4*v + 4] = m.w;
        }
        a[0]  = cL ? rowA[-1] : 0.0f;
        a[17] = cR ? rowA[16] : 0.0f;
    } else {
        #pragma unroll
        for (int k = 0; k < 18; k++) a[k] = 0.0f;
    }

    if (rB) {
        #pragma unroll
        for (int v = 0; v < 4; v++) {
            float4 m = reinterpret_cast<const float4*>(rowB)[v];
            b[4*v + 1] = m.x; b[4*v + 2] = m.y; b[4*v + 3] = m.z; b[4*v + 4] = m.w;
        }
        b[0]  = cL ? rowB[-1] : 0.0f;
        b[17] = cR ? rowB[16] : 0.0f;
    } else {
        #pragma unroll
        for (int k = 0; k < 18; k++) b[k] = 0.0f;
    }

    const size_t obase = (size_t)bc * (OH_ * OW_);
    float* rOdd  = out + obase + (size_t)(2 * p - 1) * OW_ + tx * 32;  // row 2p-1
    float* rEven = rOdd + OW_;                                          // row 2p

    // 8 chunks of 4 output cols per row. Chunk c covers output cols
    // 32*tx + 4c .. +3, from local inputs a[2c .. 2c+3].
    #pragma unroll
    for (int c = 0; c < 8; c++) {
        const int j = 2 * c;
        float hA0 = 0.25f * a[j]     + 0.75f * a[j + 1];
        float hA1 = 0.75f * a[j + 1] + 0.25f * a[j + 2];
        float hA2 = 0.25f * a[j + 1] + 0.75f * a[j + 2];
        float hA3 = 0.75f * a[j + 2] + 0.25f * a[j + 3];
        float hB0 = 0.25f * b[j]     + 0.75f * b[j + 1];
        float hB1 = 0.75f * b[j + 1] + 0.25f * b[j + 2];
        float hB2 = 0.25f * b[j + 1] + 0.75f * b[j + 2];
        float hB3 = 0.75f * b[j + 2] + 0.25f * b[j + 3];

        if (p >= 1) {   // output row 2p-1: 0.75*A + 0.25*B
            float4 v;
            v.x = 0.75f * hA0 + 0.25f * hB0;
            v.y = 0.75f * hA1 + 0.25f * hB1;
            v.z = 0.75f * hA2 + 0.25f * hB2;
            v.w = 0.75f * hA3 + 0.25f * hB3;
            reinterpret_cast<float4*>(rOdd)[c] = v;
        }
        if (p < H_) {   // output row 2p: 0.25*A + 0.75*B
            float4 v;
            v.x = 0.25f * hA0 + 0.75f * hB0;
            v.y = 0.25f * hA1 + 0.75f * hB1;
            v.z = 0.25f * hA2 + 0.75f * hB2;
            v.w = 0.25f * hA3 + 0.75f * hB3;
            reinterpret_cast<float4*>(rEven)[c] = v;
        }
    }
}

extern "C" void kernel_launch(void* const* d_in, const int* in_sizes, int n_in,
                              void* d_out, int out_size) {
    const float* x = (const float*)d_in[0];
    // d_in[1] is the 4x4 FIR kernel; fixed by setup_inputs, separable 1D taps
    // [0.25, 0.75] are baked into the kernel above.
    float* out = (float*)d_out;

    dim3 block(8, 16, 1);                       // 128 threads
    dim3 grid(1, (129 + 15) / 16, BC_);         // 129 row-pairs, 2048 images
    up2_kernel<<<grid, block>>>(x, out);
}

// round 4
// speedup vs baseline: 2.3000x; 2.3000x over previous
#include <cuda_runtime.h>
#include <cuda_bf16.h>

// Upsample_910533067305: upfirdn2d(x, k=[1,3,3,1]^T[1,3,3,1]/16*4, up=2, pad=(2,1))
// Separable 2-tap blends:
//   out[2i]   = 0.25*x[i-1] + 0.75*x[i]
//   out[2i+1] = 0.75*x[i]   + 0.25*x[i+1]
// One warp owns a full 128-col row strip (lane tx -> aligned float4 at col 4*tx,
// fully coalesced) and marches down 17 consecutive row-pairs, rolling the lower
// input row to the upper in registers. Per pair: 1 vector load + 2 scalar halo
// loads + 4 vector stores (vs 2 + 4 + 4 in the 121us version).

#define BC_   2048   // 16*128 images
#define H_    128
#define W_    128
#define OH_   256
#define OW_   256
#define PAIRS_PER_WARP 17   // ceil(129 / 8)

__global__ __launch_bounds__(256)
void up2_roll_kernel(const float* __restrict__ x, float* __restrict__ out) {
    const int tx = threadIdx.x;        // 0..31: lane owns cols 4tx..4tx+3
    const int wy = threadIdx.y;        // 0..7:  warp's pair-segment
    const int bc = blockIdx.x;         // image 0..2047

    const int ps = wy * PAIRS_PER_WARP;
    int pe = ps + PAIRS_PER_WARP;
    if (pe > H_ + 1) pe = H_ + 1;      // pairs p in [ps, pe), p uses rows p-1, p

    const float* base  = x   + (size_t)bc * (H_ * W_);
    float*       obase = out + (size_t)bc * (OH_ * OW_);
    const int ix = tx * 4;

    // v[k] = input col (ix-1+k) of row r; zeros outside the image.
    auto loadrow = [&](int r, float v[6]) {
        if (r < 0 || r >= H_) {
            v[0] = v[1] = v[2] = v[3] = v[4] = v[5] = 0.0f;
            return;
        }
        const float* rp = base + (size_t)r * W_;
        float4 m = *reinterpret_cast<const float4*>(rp + ix);
        v[1] = m.x; v[2] = m.y; v[3] = m.z; v[4] = m.w;
        v[0] = (tx > 0)  ? __ldg(rp + ix - 1) : 0.0f;
        v[5] = (tx < 31) ? __ldg(rp + ix + 4) : 0.0f;
    };

    float a[6], b[6], c[6];
    loadrow(ps - 1, a);                // upper row of first pair
    loadrow(ps, b);                    // lower row of first pair

    for (int p = ps; p < pe; ++p) {
        // Prefetch the next pair's lower row while blending the current pair.
        const bool more = (p + 1 < pe);
        if (more) loadrow(p + 1, c);

        // Horizontal blends for both rows: 8 output cols per lane.
        float hA[8], hB[8];
        #pragma unroll
        for (int j = 0; j < 4; j++) {
            hA[2*j]     = 0.25f * a[j]     + 0.75f * a[j + 1];
            hA[2*j + 1] = 0.75f * a[j + 1] + 0.25f * a[j + 2];
            hB[2*j]     = 0.25f * b[j]     + 0.75f * b[j + 1];
            hB[2*j + 1] = 0.75f * b[j + 1] + 0.25f * b[j + 2];
        }

        const int oxo = tx * 8;

        if (p >= 1) {                  // output row 2p-1: 0.75*A + 0.25*B
            float* r = obase + (size_t)(2 * p - 1) * OW_ + oxo;
            float4 v0, v1;
            v0.x = 0.75f*hA[0] + 0.25f*hB[0];
            v0.y = 0.75f*hA[1] + 0.25f*hB[1];
            v0.z = 0.75f*hA[2] + 0.25f*hB[2];
            v0.w = 0.75f*hA[3] + 0.25f*hB[3];
            v1.x = 0.75f*hA[4] + 0.25f*hB[4];
            v1.y = 0.75f*hA[5] + 0.25f*hB[5];
            v1.z = 0.75f*hA[6] + 0.25f*hB[6];
            v1.w = 0.75f*hA[7] + 0.25f*hB[7];
            reinterpret_cast<float4*>(r)[0] = v0;
            reinterpret_cast<float4*>(r)[1] = v1;
        }
        if (p < H_) {                  // output row 2p: 0.25*A + 0.75*B
            float* r = obase + (size_t)(2 * p) * OW_ + oxo;
            float4 v0, v1;
            v0.x = 0.25f*hA[0] + 0.75f*hB[0];
            v0.y = 0.25f*hA[1] + 0.75f*hB[1];
            v0.z = 0.25f*hA[2] + 0.75f*hB[2];
            v0.w = 0.25f*hA[3] + 0.75f*hB[3];
            v1.x = 0.25f*hA[4] + 0.75f*hB[4];
            v1.y = 0.25f*hA[5] + 0.75f*hB[5];
            v1.z = 0.25f*hA[6] + 0.75f*hB[6];
            v1.w = 0.25f*hA[7] + 0.75f*hB[7];
            reinterpret_cast<float4*>(r)[0] = v0;
            reinterpret_cast<float4*>(r)[1] = v1;
        }

        // Roll: lower row becomes upper, prefetched row becomes lower.
        #pragma unroll
        for (int k = 0; k < 6; k++) { a[k] = b[k]; b[k] = c[k]; }
    }
}

extern "C" void kernel_launch(void* const* d_in, const int* in_sizes, int n_in,
                              void* d_out, int out_size) {
    const float* x = (const float*)d_in[0];
    // d_in[1] is the 4x4 FIR kernel; fixed by setup_inputs, separable 1D taps
    // [0.25, 0.75] are baked in above.
    float* out = (float*)d_out;

    dim3 block(32, 8, 1);              // 8 warps; each owns 17 row-pairs
    dim3 grid(BC_, 1, 1);              // one block per image
    up2_roll_kernel<<<grid, block>>>(x, out);
}

// round 5
// speedup vs baseline: 2.5526x; 1.1098x over previous
#include <cuda_runtime.h>
#include <cuda_bf16.h>

// Upsample_910533067305: upfirdn2d(x, k=[1,3,3,1]^T[1,3,3,1]/16*4, up=2, pad=(2,1))
// Separable 2-tap blends:
//   out[2i]   = 0.25*x[i-1] + 0.75*x[i]
//   out[2i+1] = 0.75*x[i]   + 0.25*x[i+1]
// Output rows (2p-1, 2p) share input rows (p-1, p): compute both per thread.
// Identical structure to the 121us R1 kernel; stores use st.global.wt to
// bypass L2 for the write-once output stream.

#define BC_   2048   // 16*128
#define H_    128
#define W_    128
#define OH_   256
#define OW_   256

__global__ __launch_bounds__(256)
void up2_kernel(const float* __restrict__ x, float* __restrict__ out) {
    const int tx = threadIdx.x;                            // 0..31, 8 output cols each
    const int p  = blockIdx.y * blockDim.y + threadIdx.y;  // row-pair index 0..128
    if (p > H_) return;
    const int bc = blockIdx.z;

    const int iy = p - 1;          // upper input row of the pair
    const int ix = tx * 4;         // first input col of the aligned float4

    const float* base = x + (size_t)bc * (H_ * W_);
    const float* rowA = base + (size_t)iy * W_;
    const float* rowB = rowA + W_;

    float a[6], b[6];
    const bool rA = (iy >= 0);
    const bool rB = (iy + 1 < H_);
    const bool cL = (ix > 0);
    const bool cR = (ix + 4 < W_);

    if (rA) {
        float4 m = *reinterpret_cast<const float4*>(rowA + ix);
        a[1] = m.x; a[2] = m.y; a[3] = m.z; a[4] = m.w;
        a[0] = cL ? __ldg(rowA + ix - 1) : 0.0f;
        a[5] = cR ? __ldg(rowA + ix + 4) : 0.0f;
    } else {
        a[0] = a[1] = a[2] = a[3] = a[4] = a[5] = 0.0f;
    }
    if (rB) {
        float4 m = *reinterpret_cast<const float4*>(rowB + ix);
        b[1] = m.x; b[2] = m.y; b[3] = m.z; b[4] = m.w;
        b[0] = cL ? __ldg(rowB + ix - 1) : 0.0f;
        b[5] = cR ? __ldg(rowB + ix + 4) : 0.0f;
    } else {
        b[0] = b[1] = b[2] = b[3] = b[4] = b[5] = 0.0f;
    }

    // Horizontal blends: 8 output cols per row, from cols ix-1..ix+4.
    float hA[8], hB[8];
    #pragma unroll
    for (int j = 0; j < 4; j++) {
        hA[2*j]     = 0.25f * a[j]     + 0.75f * a[j + 1];
        hA[2*j + 1] = 0.75f * a[j + 1] + 0.25f * a[j + 2];
        hB[2*j]     = 0.25f * b[j]     + 0.75f * b[j + 1];
        hB[2*j + 1] = 0.75f * b[j + 1] + 0.25f * b[j + 2];
    }

    const size_t obase = (size_t)bc * (OH_ * OW_);
    const int oxo = tx * 8;

    // Output row 2p-1 (odd): 0.75*rowA + 0.25*rowB
    if (p >= 1) {
        float* r = out + obase + (size_t)(2 * p - 1) * OW_ + oxo;
        float4 v0, v1;
        v0.x = 0.75f*hA[0] + 0.25f*hB[0];
        v0.y = 0.75f*hA[1] + 0.25f*hB[1];
        v0.z = 0.75f*hA[2] + 0.25f*hB[2];
        v0.w = 0.75f*hA[3] + 0.25f*hB[3];
        v1.x = 0.75f*hA[4] + 0.25f*hB[4];
        v1.y = 0.75f*hA[5] + 0.25f*hB[5];
        v1.z = 0.75f*hA[6] + 0.25f*hB[6];
        v1.w = 0.75f*hA[7] + 0.25f*hB[7];
        __stwt(reinterpret_cast<float4*>(r),     v0);
        __stwt(reinterpret_cast<float4*>(r) + 1, v1);
    }

    // Output row 2p (even): 0.25*rowA + 0.75*rowB
    if (p < H_) {
        float* r = out + obase + (size_t)(2 * p) * OW_ + oxo;
        float4 v0, v1;
        v0.x = 0.25f*hA[0] + 0.75f*hB[0];
        v0.y = 0.25f*hA[1] + 0.75f*hB[1];
        v0.z = 0.25f*hA[2] + 0.75f*hB[2];
        v0.w = 0.25f*hA[3] + 0.75f*hB[3];
        v1.x = 0.25f*hA[4] + 0.75f*hB[4];
        v1.y = 0.25f*hA[5] + 0.75f*hB[5];
        v1.z = 0.25f*hA[6] + 0.75f*hB[6];
        v1.w = 0.25f*hA[7] + 0.75f*hB[7];
        __stwt(reinterpret_cast<float4*>(r),     v0);
        __stwt(reinterpret_cast<float4*>(r) + 1, v1);
    }
}

extern "C" void kernel_launch(void* const* d_in, const int* in_sizes, int n_in,
                              void* d_out, int out_size) {
    const float* x = (const float*)d_in[0];
    // d_in[1] is the 4x4 FIR kernel; fixed by setup_inputs, separable 1D taps
    // [0.25, 0.75] are baked into the kernel above.
    float* out = (float*)d_out;

    dim3 block(32, 8, 1);                       // 256 threads
    dim3 grid(1, (129 + 7) / 8, BC_);           // 129 row-pairs, 2048 images
    up2_kernel<<<grid, block>>>(x, out);
}

// round 6
// speedup vs baseline: 2.9054x; 1.1382x over previous
#include <cuda_runtime.h>
#include <cuda_bf16.h>

// Upsample_910533067305: upfirdn2d(x, k=[1,3,3,1]^T[1,3,3,1]/16*4, up=2, pad=(2,1))
// Separable 2-tap blends:
//   out[2i]   = 0.25*x[i-1] + 0.75*x[i]
//   out[2i+1] = 0.75*x[i]   + 0.25*x[i+1]
// Output rows (2p-1, 2p) share input rows (p-1, p): compute both per thread.
// Same structure as the 121us R1 kernel, but the 4 misaligned scalar halo LDGs
// are replaced by a conflict-free smem edge exchange (2x STS.64 + 2x LDS.64).

#define BC_   2048   // 16*128
#define H_    128
#define W_    128
#define OH_   256
#define OW_   256

__global__ __launch_bounds__(256)
void up2_kernel(const float* __restrict__ x, float* __restrict__ out) {
    __shared__ float2 sX[8][32];   // per warp: {rowA.x, rowB.x} of each lane
    __shared__ float2 sW[8][32];   // per warp: {rowA.w, rowB.w} of each lane

    const int tx = threadIdx.x;                            // 0..31, 8 output cols each
    const int wy = threadIdx.y;                            // warp id in block
    const int p  = blockIdx.y * blockDim.y + wy;           // row-pair index 0..128 (warp-uniform)
    if (p > H_) return;                                    // whole warp exits together
    const int bc = blockIdx.z;

    const int iy = p - 1;          // upper input row of the pair
    const int ix = tx * 4;         // first input col of the aligned float4

    const float* base = x + (size_t)bc * (H_ * W_);
    const float* rowA = base + (size_t)iy * W_;
    const float* rowB = rowA + W_;

    const bool rA = (iy >= 0);
    const bool rB = (iy + 1 < H_);

    float4 ma = rA ? *reinterpret_cast<const float4*>(rowA + ix)
                   : make_float4(0.f, 0.f, 0.f, 0.f);
    float4 mb = rB ? *reinterpret_cast<const float4*>(rowB + ix)
                   : make_float4(0.f, 0.f, 0.f, 0.f);

    // Edge exchange: halo col ix-1 is lane tx-1's .w; halo col ix+4 is lane tx+1's .x.
    sX[wy][tx] = make_float2(ma.x, mb.x);
    sW[wy][tx] = make_float2(ma.w, mb.w);
    __syncwarp();
    float2 lft = sW[wy][(tx + 31) & 31];   // lane tx-1 (wrapped; lane 0 zeroed below)
    float2 rgt = sX[wy][(tx + 1) & 31];    // lane tx+1 (wrapped; lane 31 zeroed below)
    if (tx == 0)  lft = make_float2(0.f, 0.f);   // col -1 -> zero pad
    if (tx == 31) rgt = make_float2(0.f, 0.f);   // col 128 -> zero pad

    float a[6] = { lft.x, ma.x, ma.y, ma.z, ma.w, rgt.x };
    float b[6] = { lft.y, mb.x, mb.y, mb.z, mb.w, rgt.y };

    // Horizontal blends: 8 output cols per row, from cols ix-1..ix+4.
    float hA[8], hB[8];
    #pragma unroll
    for (int j = 0; j < 4; j++) {
        hA[2*j]     = 0.25f * a[j]     + 0.75f * a[j + 1];
        hA[2*j + 1] = 0.75f * a[j + 1] + 0.25f * a[j + 2];
        hB[2*j]     = 0.25f * b[j]     + 0.75f * b[j + 1];
        hB[2*j + 1] = 0.75f * b[j + 1] + 0.25f * b[j + 2];
    }

    const size_t obase = (size_t)bc * (OH_ * OW_);
    const int oxo = tx * 8;

    // Output row 2p-1 (odd): 0.75*rowA + 0.25*rowB
    if (p >= 1) {
        float* r = out + obase + (size_t)(2 * p - 1) * OW_ + oxo;
        float4 v0, v1;
        v0.x = 0.75f*hA[0] + 0.25f*hB[0];
        v0.y = 0.75f*hA[1] + 0.25f*hB[1];
        v0.z = 0.75f*hA[2] + 0.25f*hB[2];
        v0.w = 0.75f*hA[3] + 0.25f*hB[3];
        v1.x = 0.75f*hA[4] + 0.25f*hB[4];
        v1.y = 0.75f*hA[5] + 0.25f*hB[5];
        v1.z = 0.75f*hA[6] + 0.25f*hB[6];
        v1.w = 0.75f*hA[7] + 0.25f*hB[7];
        reinterpret_cast<float4*>(r)[0] = v0;
        reinterpret_cast<float4*>(r)[1] = v1;
    }

    // Output row 2p (even): 0.25*rowA + 0.75*rowB
    if (p < H_) {
        float* r = out + obase + (size_t)(2 * p) * OW_ + oxo;
        float4 v0, v1;
        v0.x = 0.25f*hA[0] + 0.75f*hB[0];
        v0.y = 0.25f*hA[1] + 0.75f*hB[1];
        v0.z = 0.25f*hA[2] + 0.75f*hB[2];
        v0.w = 0.25f*hA[3] + 0.75f*hB[3];
        v1.x = 0.25f*hA[4] + 0.75f*hB[4];
        v1.y = 0.25f*hA[5] + 0.75f*hB[5];
        v1.z = 0.25f*hA[6] + 0.75f*hB[6];
        v1.w = 0.25f*hA[7] + 0.75f*hB[7];
        reinterpret_cast<float4*>(r)[0] = v0;
        reinterpret_cast<float4*>(r)[1] = v1;
    }
}

extern "C" void kernel_launch(void* const* d_in, const int* in_sizes, int n_in,
                              void* d_out, int out_size) {
    const float* x = (const float*)d_in[0];
    // d_in[1] is the 4x4 FIR kernel; fixed by setup_inputs, separable 1D taps
    // [0.25, 0.75] are baked into the kernel above.
    float* out = (float*)d_out;

    dim3 block(32, 8, 1);                       // 256 threads
    dim3 grid(1, (129 + 7) / 8, BC_);           // 129 row-pairs, 2048 images
    up2_kernel<<<grid, block>>>(x, out);
}